// round 16
// baseline (speedup 1.0000x reference)
#include <cuda_runtime.h>
#include <math.h>

typedef unsigned long long u64;

#define NB 64
#define NC 64
#define NT 512
#define NV 25
#define NK 3
#define NO 64

// -------- scratch (device globals) --------
__device__ float g_Y[(size_t)NB * NO * NT * NV];   // GCN output after BN+hswish

__device__ __forceinline__ float hswish(float x) {
    return x * fminf(fmaxf(x + 3.0f, 0.0f), 6.0f) * (1.0f / 6.0f);
}
__device__ __forceinline__ u64 ffma2(u64 a, u64 b, u64 c) {
    u64 d; asm("fma.rn.f32x2 %0, %1, %2, %3;" : "=l"(d) : "l"(a), "l"(b), "l"(c)); return d;
}
__device__ __forceinline__ u64 dup2(float v) {
    u64 d; asm("mov.b64 %0, {%1, %1};" : "=l"(d) : "f"(v)); return d;
}
__device__ __forceinline__ void unpk(u64 p, float& lo, float& hi) {
    asm("mov.b64 {%0, %1}, %2;" : "=f"(lo), "=f"(hi) : "l"(p));
}

// ===================== K1: GCN v2 — 3 blocks/SM =====================
// grid (T/TT, B), 256 thr. k loop outermost; W staged per-k (prefetch under stage B).
// smem floats:
//   Xs [64][100] @0      6400
//   Uk [64][100] @6400   6400
//   Wk [64][64]  @12800  4096   (current k only)
//   An [75][28]  @16896  2100   (w stride 28 = 112B, 16B-aligned rows; pads 0)
//   dsh[80]      @18996  80
//   total 19076 fl = 76,304 B  -> 3 blocks/SM (228.9 KB)
#define TT 4
#define P1 100
#define GC_UK 6400
#define GC_WK 12800
#define GC_AN 16896
#define GC_DSH 18996
#define GC_TOT 19076

__global__ void __launch_bounds__(256, 3)
gcn_kernel(const float* __restrict__ x,
           const float* __restrict__ Af, const float* __restrict__ Al,
           const float* __restrict__ Wg,
           const float* __restrict__ gscale, const float* __restrict__ gbias) {
    extern __shared__ float sm[];
    float* Xs = sm;
    float* Uk = sm + GC_UK;
    float* Wk = sm + GC_WK;
    float* An = sm + GC_AN;
    float* dsh = sm + GC_DSH;

    int tid = threadIdx.x;
    int t0 = blockIdx.x * TT;
    int b = blockIdx.y;

    // ---- D^{-1/2} row factors ----
    if (tid < NK * NV) {
        const float* af = Af + tid * NV;
        const float* al = Al + tid * NV;
        float s = 0.0f;
        #pragma unroll
        for (int w = 0; w < NV; w++) s += fabsf(af[w] + al[w]);
        dsh[tid] = rsqrtf(fmaxf(s, 1e-6f));
    }
    // ---- cooperative loads: Xs + W_0 ----
    {
        const float4* xsrc = (const float4*)(x + ((size_t)b * NC * NT + t0) * NV);
        for (int i = tid; i < 1600; i += 256) {
            int c = i / 25, q = i - c * 25;
            ((float4*)Xs)[i] = xsrc[c * 3200 + q];
        }
        const float4* wsrc = (const float4*)Wg;   // k=0 slice
        #pragma unroll
        for (int q = 0; q < 4; q++) ((float4*)Wk)[tid + q * 256] = wsrc[tid + q * 256];
    }
    __syncthreads();
    // ---- An fill (stride 28): An[k*25+v][w] = dsh[k,v]*|Af+Al|*dsh[k,w]; pads 0 ----
    for (int i = tid; i < NK * NV * 28; i += 256) {
        int row = i / 28;          // k*25+v
        int w = i - row * 28;
        float val = 0.0f;
        if (w < NV) {
            int k = row / NV;
            int src = row * NV + w;
            val = dsh[row] * fabsf(Af[src] + Al[src]) * dsh[k * NV + w];
        }
        An[i] = val;
    }
    __syncthreads();

    int jg = tid >> 5, pt = tid & 31;
    bool hiok = (pt < 18);          // second col-pair (64+2pt,65+2pt) < 100
    int o = tid >> 2, ttl = tid & 3;

    u64 bacc[14];
    #pragma unroll
    for (int j = 0; j < 14; j++) bacc[j] = 0ull;

    for (int k = 0; k < NK; k++) {
        // ---- stage A: Uk[o][p] = sum_c Wk[o][c] * Xs[c][p] ----
        u64 acc[8][2];
        #pragma unroll
        for (int r = 0; r < 8; r++) { acc[r][0] = 0ull; acc[r][1] = 0ull; }
        const float* Wr = Wk + (jg * 8) * 64;
        for (int c4 = 0; c4 < 16; c4++) {
            u64 xv0[4], xv1[4];
            #pragma unroll
            for (int cc = 0; cc < 4; cc++) {
                const float* xp = Xs + (c4 * 4 + cc) * P1;
                xv0[cc] = *(const u64*)(xp + 2 * pt);
                xv1[cc] = hiok ? *(const u64*)(xp + 64 + 2 * pt) : 0ull;
            }
            #pragma unroll
            for (int r = 0; r < 8; r++) {
                float4 w4 = *(const float4*)(Wr + r * 64 + c4 * 4);
                u64 w;
                w = dup2(w4.x); acc[r][0] = ffma2(w, xv0[0], acc[r][0]); acc[r][1] = ffma2(w, xv1[0], acc[r][1]);
                w = dup2(w4.y); acc[r][0] = ffma2(w, xv0[1], acc[r][0]); acc[r][1] = ffma2(w, xv1[1], acc[r][1]);
                w = dup2(w4.z); acc[r][0] = ffma2(w, xv0[2], acc[r][0]); acc[r][1] = ffma2(w, xv1[2], acc[r][1]);
                w = dup2(w4.w); acc[r][0] = ffma2(w, xv0[3], acc[r][0]); acc[r][1] = ffma2(w, xv1[3], acc[r][1]);
            }
        }
        #pragma unroll
        for (int r = 0; r < 8; r++) {
            float* up = Uk + (jg * 8 + r) * P1;
            *(u64*)(up + 2 * pt) = acc[r][0];
            if (hiok) *(u64*)(up + 64 + 2 * pt) = acc[r][1];
        }
        __syncthreads();

        // ---- prefetch W_{k+1} (Wk only read by stage A; safe to overwrite here) ----
        float4 wpre[4];
        if (k < NK - 1) {
            const float4* wsrc = (const float4*)(Wg + (size_t)(k + 1) * 4096);
            #pragma unroll
            for (int q = 0; q < 4; q++) wpre[q] = wsrc[tid + q * 256];
        }

        // ---- stage B: bacc[o][tt][w-pairs] += Uk[o][tt*25+v] * An[k][v][w] ----
        {
            const float* Ur = Uk + o * P1 + ttl * NV;
            const float* Ar = An + k * (NV * 28);
            #pragma unroll 5
            for (int v = 0; v < NV; v++) {
                u64 uv = dup2(Ur[v]);
                const ulonglong2* A2 = (const ulonglong2*)(Ar + v * 28);
                #pragma unroll
                for (int q = 0; q < 7; q++) {
                    ulonglong2 aa = A2[q];
                    bacc[2 * q]     = ffma2(uv, aa.x, bacc[2 * q]);
                    bacc[2 * q + 1] = ffma2(uv, aa.y, bacc[2 * q + 1]);
                }
            }
        }
        if (k < NK - 1) {
            #pragma unroll
            for (int q = 0; q < 4; q++) ((float4*)Wk)[tid + q * 256] = wpre[q];
        }
        __syncthreads();
    }

    // ---- epilogue: BN + hswish -> stage to Xs -> coalesced float4 store ----
    {
        float s = gscale[o] * (1.0f / 3.0f);   // fold 1/K
        float bi = gbias[o];
        float* yrow = Xs + o * P1 + ttl * NV;
        #pragma unroll
        for (int j = 0; j < 13; j++) {
            float lo, hi; unpk(bacc[j], lo, hi);
            yrow[2 * j] = hswish(lo * s + bi);
            if (2 * j + 1 < NV) yrow[2 * j + 1] = hswish(hi * s + bi);
        }
    }
    __syncthreads();
    {
        float4* ydst = (float4*)(g_Y + ((size_t)b * NO * NT + t0) * NV);
        for (int i = tid; i < 1600; i += 256) {
            int oo = i / 25, q = i - oo * 25;
            ydst[oo * 3200 + q] = ((const float4*)Xs)[i];
        }
    }
}

// ===================== K2: TCN (R15 winner, verbatim) =====================
// grid (T/4, B), 256 thr, 3 blocks/SM (46.1 KB smem).
#define TT2 4
#define P2 100
#define TC_PWS 6400
#define TC_DW 10496
#define TC_PR 11264
#define TC_TOT 11520

__global__ void __launch_bounds__(256, 3)
tcn_kernel(const float* __restrict__ x, const float* __restrict__ dwg,
           const float* __restrict__ pwg, const float* __restrict__ s1g,
           const float* __restrict__ b1g, const float* __restrict__ s2g,
           const float* __restrict__ b2g, float* __restrict__ out) {
    extern __shared__ float sm[];
    float* T1 = sm;
    float* Pws = sm + TC_PWS;
    float* Dw = sm + TC_DW;
    float* PR = sm + TC_PR;  // S1 | B1 | S2 | B2

    int tid = threadIdx.x;
    int t0 = blockIdx.x * TT2;
    int b = blockIdx.y;

    // ---- param loads ----
    {
        const float4* psrc = (const float4*)pwg;
        for (int i = tid; i < 1024; i += 256) ((float4*)Pws)[i] = psrc[i];
    }
    for (int i = tid; i < NO * 9; i += 256) {
        int c = i / 9, j = i - c * 9;
        Dw[c * 12 + j] = dwg[i];
    }
    if (tid < 64) {
        PR[tid]       = s1g[tid];
        PR[64 + tid]  = b1g[tid];
        PR[128 + tid] = s2g[tid];
        PR[192 + tid] = b2g[tid];
    }
    __syncthreads();

    // ---- depthwise k=9 + BN1 + hswish -> T1 (sliding window, direct g_Y reads) ----
    bool interior = (blockIdx.x > 0) && (blockIdx.x < (int)gridDim.x - 1);
    #pragma unroll 1
    for (int it = 0; it < 7; it++) {
        int i = tid + it * 256;
        if (i < 1600) {
            int c = i / 25, v = i - c * 25;
            const float* dr = Dw + c * 12;
            const float* ybase = g_Y + (((size_t)b * NO + c) * NT + t0 - 4) * NV + v;
            float w[12];
            if (interior) {
                #pragma unroll
                for (int j = 0; j < 12; j++) w[j] = __ldg(ybase + j * NV);
            } else {
                #pragma unroll
                for (int j = 0; j < 12; j++) {
                    int tg = t0 - 4 + j;
                    w[j] = (tg >= 0 && tg < NT) ? __ldg(ybase + j * NV) : 0.0f;
                }
            }
            float sc1 = PR[c], bb1 = PR[64 + c];
            #pragma unroll
            for (int tt = 0; tt < TT2; tt++) {
                float a = 0.0f;
                #pragma unroll
                for (int j = 0; j < 9; j++) a = fmaf(w[tt + j], dr[j], a);
                T1[c * P2 + tt * NV + v] = hswish(a * sc1 + bb1);
            }
        }
    }
    __syncthreads();

    // ---- pointwise 64x64 + BN2 + residual + hswish ----
    int og = tid >> 5, pt = tid & 31;
    bool hiok = (pt < 18);
    u64 acc[8][2];
    #pragma unroll
    for (int r = 0; r < 8; r++) { acc[r][0] = 0ull; acc[r][1] = 0ull; }

    for (int c4 = 0; c4 < 16; c4++) {
        u64 tv0[4], tv1[4];
        #pragma unroll
        for (int cc = 0; cc < 4; cc++) {
            const float* tp = T1 + (c4 * 4 + cc) * P2;
            tv0[cc] = *(const u64*)(tp + 2 * pt);
            tv1[cc] = hiok ? *(const u64*)(tp + 64 + 2 * pt) : 0ull;
        }
        #pragma unroll
        for (int r = 0; r < 8; r++) {
            float4 w4 = *(const float4*)(Pws + (og * 8 + r) * 64 + c4 * 4);
            u64 w;
            w = dup2(w4.x); acc[r][0] = ffma2(w, tv0[0], acc[r][0]); acc[r][1] = ffma2(w, tv1[0], acc[r][1]);
            w = dup2(w4.y); acc[r][0] = ffma2(w, tv0[1], acc[r][0]); acc[r][1] = ffma2(w, tv1[1], acc[r][1]);
            w = dup2(w4.z); acc[r][0] = ffma2(w, tv0[2], acc[r][0]); acc[r][1] = ffma2(w, tv1[2], acc[r][1]);
            w = dup2(w4.w); acc[r][0] = ffma2(w, tv0[3], acc[r][0]); acc[r][1] = ffma2(w, tv1[3], acc[r][1]);
        }
    }

    #pragma unroll
    for (int r = 0; r < 8; r++) {
        int oo = og * 8 + r;
        float sc = PR[128 + oo], bb = PR[192 + oo];
        size_t base = (((size_t)b * NC + oo) * NT + t0) * NV;
        {
            float lo, hi; unpk(acc[r][0], lo, hi);
            float2 xa = *(const float2*)(x + base + 2 * pt);
            float2 res = make_float2(hswish(lo * sc + bb + xa.x),
                                     hswish(hi * sc + bb + xa.y));
            *(float2*)(out + base + 2 * pt) = res;
        }
        if (hiok) {
            float lo, hi; unpk(acc[r][1], lo, hi);
            float2 xa = *(const float2*)(x + base + 64 + 2 * pt);
            float2 res = make_float2(hswish(lo * sc + bb + xa.x),
                                     hswish(hi * sc + bb + xa.y));
            *(float2*)(out + base + 64 + 2 * pt) = res;
        }
    }
}

// ===================== launcher =====================
extern "C" void kernel_launch(void* const* d_in, const int* in_sizes, int n_in,
                              void* d_out, int out_size) {
    const float* x  = (const float*)d_in[0];
    const float* Af = (const float*)d_in[1];
    const float* Al = (const float*)d_in[2];
    const float* Wg = (const float*)d_in[3];
    const float* gs = (const float*)d_in[4];
    const float* gb = (const float*)d_in[5];
    const float* dw = (const float*)d_in[6];
    const float* pw = (const float*)d_in[7];
    const float* s1 = (const float*)d_in[8];
    const float* b1 = (const float*)d_in[9];
    const float* s2 = (const float*)d_in[10];
    const float* b2 = (const float*)d_in[11];
    float* out = (float*)d_out;

    (void)in_sizes; (void)n_in; (void)out_size;

    cudaFuncSetAttribute(gcn_kernel, cudaFuncAttributeMaxDynamicSharedMemorySize,
                         GC_TOT * (int)sizeof(float));
    cudaFuncSetAttribute(tcn_kernel, cudaFuncAttributeMaxDynamicSharedMemorySize,
                         TC_TOT * (int)sizeof(float));

    gcn_kernel<<<dim3(NT / TT, NB), 256, GC_TOT * sizeof(float)>>>(x, Af, Al, Wg, gs, gb);
    tcn_kernel<<<dim3(NT / TT2, NB), 256, TC_TOT * sizeof(float)>>>(x, dw, pw, s1, b1, s2, b2, out);
}